// round 16
// baseline (speedup 1.0000x reference)
#include <cuda_runtime.h>
#include <cuda_fp16.h>
#include <cstdint>

#define MDIM 16384
#define NDIM 4096
#define KDIM 4096

// Module-load scratch (allowed): fp16 copies of x and expanded weight.
__device__ __half g_xh[(size_t)MDIM * KDIM];    // 128 MB, [M, K] row-major
__device__ __half g_wh[(size_t)NDIM * KDIM];    // 32 MB,  [N, K] row-major

// ---------------------------------------------------------------------------
// helpers
// ---------------------------------------------------------------------------
__device__ __forceinline__ uint32_t smem_u32(const void* p) {
    uint32_t a;
    asm("{ .reg .u64 t; cvta.to.shared.u64 t, %1; cvt.u32.u64 %0, t; }" : "=r"(a) : "l"(p));
    return a;
}
__device__ __forceinline__ void cp16(uint32_t s, const void* g) {
    asm volatile("cp.async.cg.shared.global [%0], [%1], 16;" :: "r"(s), "l"(g) : "memory");
}
#define CP_COMMIT() asm volatile("cp.async.commit_group;" ::: "memory")

__device__ __forceinline__ void ldsm4(uint32_t* r, uint32_t addr) {
    asm volatile("ldmatrix.sync.aligned.m8n8.x4.shared.b16 {%0,%1,%2,%3}, [%4];"
        : "=r"(r[0]), "=r"(r[1]), "=r"(r[2]), "=r"(r[3]) : "r"(addr));
}
__device__ __forceinline__ void mma_f16(float* d, const uint32_t* a, const uint32_t* b) {
    asm volatile(
        "mma.sync.aligned.m16n8k16.row.col.f32.f16.f16.f32 "
        "{%0,%1,%2,%3}, {%4,%5,%6,%7}, {%8,%9}, {%0,%1,%2,%3};"
        : "+f"(d[0]), "+f"(d[1]), "+f"(d[2]), "+f"(d[3])
        : "r"(a[0]), "r"(a[1]), "r"(a[2]), "r"(a[3]), "r"(b[0]), "r"(b[1]));
}

// ---------------------------------------------------------------------------
// Kernel 0: convert x fp32 -> fp16 (RN). 8 elements per thread.
// ---------------------------------------------------------------------------
__global__ void conv_x_kernel(const float* __restrict__ x) {
    size_t i = (size_t)blockIdx.x * blockDim.x + threadIdx.x;
    float4 a = reinterpret_cast<const float4*>(x)[2 * i];
    float4 b = reinterpret_cast<const float4*>(x)[2 * i + 1];
    __half2 h0 = __floats2half2_rn(a.x, a.y);
    __half2 h1 = __floats2half2_rn(a.z, a.w);
    __half2 h2 = __floats2half2_rn(b.x, b.y);
    __half2 h3 = __floats2half2_rn(b.z, b.w);
    uint4 o;
    o.x = *reinterpret_cast<uint32_t*>(&h0);
    o.y = *reinterpret_cast<uint32_t*>(&h1);
    o.z = *reinterpret_cast<uint32_t*>(&h2);
    o.w = *reinterpret_cast<uint32_t*>(&h3);
    reinterpret_cast<uint4*>(g_xh)[i] = o;
}

// ---------------------------------------------------------------------------
// Kernel 1: expand octonion weight [512,512,8] -> w_eff [4096,4096] in fp16.
// ---------------------------------------------------------------------------
__global__ void build_weff_kernel(const float* __restrict__ w) {
    const signed char KTAB[64] = {
        0,1,2,3,4,5,6,7, 1,0,3,2,5,4,7,6, 2,3,0,1,6,7,4,5, 3,2,1,0,7,6,5,4,
        4,5,6,7,0,1,2,3, 5,4,7,6,1,0,3,2, 6,7,4,5,2,3,0,1, 7,6,5,4,3,2,1,0 };
    const signed char STAB[64] = {
        +1,+1,+1,+1,+1,+1,+1,+1, +1,-1,+1,-1,+1,-1,-1,+1, +1,-1,-1,+1,+1,+1,-1,-1,
        +1,+1,-1,-1,+1,-1,+1,-1, +1,-1,-1,-1,-1,+1,+1,+1, +1,+1,-1,+1,-1,-1,-1,+1,
        +1,+1,+1,-1,-1,+1,-1,-1, +1,-1,+1,+1,-1,-1,+1,-1 };

    int t = blockIdx.x * blockDim.x + threadIdx.x;
    if (t >= 512 * 512) return;
    int o = t >> 9, i = t & 511;

    const float4* wp = reinterpret_cast<const float4*>(w + (size_t)t * 8);
    float4 wlo = wp[0], whi = wp[1];
    float wv[8] = {wlo.x, wlo.y, wlo.z, wlo.w, whi.x, whi.y, whi.z, whi.w};

    #pragma unroll
    for (int k = 0; k < 8; ++k) {
        __half2 h[4];
        #pragma unroll
        for (int bp = 0; bp < 4; ++bp) {
            int b0 = 2 * bp, b1 = 2 * bp + 1;
            int a0 = KTAB[k * 8 + b0], a1 = KTAB[k * 8 + b1];
            float v0 = (float)STAB[a0 * 8 + b0] * wv[a0];
            float v1 = (float)STAB[a1 * 8 + b1] * wv[a1];
            h[bp] = __floats2half2_rn(v0, v1);
        }
        uint4 pk;
        pk.x = *reinterpret_cast<uint32_t*>(&h[0]);
        pk.y = *reinterpret_cast<uint32_t*>(&h[1]);
        pk.z = *reinterpret_cast<uint32_t*>(&h[2]);
        pk.w = *reinterpret_cast<uint32_t*>(&h[3]);
        *reinterpret_cast<uint4*>(g_wh + (size_t)(o * 8 + k) * KDIM + i * 8) = pk;
    }
}

// ---------------------------------------------------------------------------
// Kernel 2: fp16 mma.sync GEMM. C[M,N] = g_xh[M,K] @ g_wh[N,K]^T + bias.
// CTA 128(M) x 64(N), BK=64 halves. 8 warps = 4(M) x 2(N); warp tile 32x32
// = 2x4 m16n8k16 atoms (32 acc regs/thread). 3-stage cp.async pipeline,
// 3 CTAs/SM (6 warps/SMSP for latency hiding).
// ---------------------------------------------------------------------------
#define BK 64
#define STAGES 3
#define A_BYTES (128 * 128)                 // 16384: 128 M-rows x 128 B
#define B_BYTES (64 * 128)                  // 8192:  64 N-rows x 128 B
#define STAGE_BYTES (A_BYTES + B_BYTES)     // 24576
#define GEMM_SMEM (STAGES * STAGE_BYTES)    // 73728
#define NTILES (KDIM / BK)                  // 64

__global__ __launch_bounds__(256, 3) void gemm_mma_kernel(
    const float* __restrict__ bias, float* __restrict__ C)
{
    extern __shared__ char smem[];
    const uint32_t sb = smem_u32(smem);
    const int tid  = threadIdx.x;
    const int lane = tid & 31;
    const int wid  = tid >> 5;
    const int rowBase = blockIdx.y * 128;    // M
    const int colBase = blockIdx.x * 64;     // N
    const int warpM = (wid >> 1) * 32;       // 4 M-warps
    const int warpN = (wid & 1) * 32;        // 2 N-warps

    // ---- global->shared load mapping ----
    // A: 128 rows x 8 chunks = 1024 cp16; thread: row tid>>1, 4 chunks at (tid&1)*4.
    const int lrA  = tid >> 1;
    const int lcpA = (tid & 1) * 4;
    const __half* gA = g_xh + (size_t)(rowBase + lrA) * KDIM + lcpA * 8;
    // B: 64 rows x 8 chunks = 512 cp16; thread: row tid>>2, 2 chunks at (tid&3)*2.
    const int lrB  = tid >> 2;
    const int lcpB = (tid & 3) * 2;
    const __half* gB = g_wh + (size_t)(colBase + lrB) * KDIM + lcpB * 8;
    uint32_t sAo[4], sBo[2];
    #pragma unroll
    for (int j = 0; j < 4; ++j)
        sAo[j] = sb + lrA * 128 + (uint32_t)(((lcpA + j) ^ (lrA & 7)) << 4);
    #pragma unroll
    for (int j = 0; j < 2; ++j)
        sBo[j] = sb + A_BYTES + lrB * 128 + (uint32_t)(((lcpB + j) ^ (lrB & 7)) << 4);

    // ---- ldmatrix address bases ----
    const int swz = lane & 7;
    uint32_t aBase[2], bBase[2];
    {
        int rA = warpM + (lane & 15);                 // lanes 16-31 -> k-chunk hi
        #pragma unroll
        for (int am = 0; am < 2; ++am)
            aBase[am] = sb + (uint32_t)((rA + am * 16) * 128);
        // B pair p covers n-atoms 2p,2p+1 (R6-verified mapping)
        int rB = warpN + (lane & 7) + ((lane >> 4) & 1) * 8;
        #pragma unroll
        for (int p = 0; p < 2; ++p)
            bBase[p] = sb + A_BYTES + (uint32_t)((rB + p * 16) * 128);
    }
    const int laneAhi = lane >> 4;           // A: k-chunk +0/+1 select
    const int laneBhi = (lane >> 3) & 1;     // B: k-chunk +0/+1 select

    float acc[2][4][4];
    #pragma unroll
    for (int am = 0; am < 2; ++am)
        #pragma unroll
        for (int an = 0; an < 4; ++an)
            #pragma unroll
            for (int e = 0; e < 4; ++e) acc[am][an][e] = 0.0f;

    // ---- prologue: prefetch tiles 0,1 into stages 0,1 ----
    #pragma unroll
    for (int t = 0; t < STAGES - 1; ++t) {
        uint32_t so = (uint32_t)(t * STAGE_BYTES);
        const __half* a = gA + t * BK;
        const __half* b = gB + t * BK;
        #pragma unroll
        for (int j = 0; j < 4; ++j) cp16(sAo[j] + so, a + j * 8);
        #pragma unroll
        for (int j = 0; j < 2; ++j) cp16(sBo[j] + so, b + j * 8);
        CP_COMMIT();
    }

    // ---- mainloop ----
    uint32_t soC = 0;
    uint32_t soP = (STAGES - 1) * STAGE_BYTES;
    #pragma unroll 1
    for (int t = 0; t < NTILES; ++t) {
        asm volatile("cp.async.wait_group 1;" ::: "memory");
        __syncthreads();

        if (t + STAGES - 1 < NTILES) {
            int tn = t + STAGES - 1;
            const __half* a = gA + tn * BK;
            const __half* b = gB + tn * BK;
            #pragma unroll
            for (int j = 0; j < 4; ++j) cp16(sAo[j] + soP, a + j * 8);
            #pragma unroll
            for (int j = 0; j < 2; ++j) cp16(sBo[j] + soP, b + j * 8);
        }
        CP_COMMIT();

        // 4 k16 steps per tile
        #pragma unroll
        for (int ks = 0; ks < 4; ++ks) {
            uint32_t a_frag[2][4], b_frag[2][4];
            const uint32_t qa = (uint32_t)(((2 * ks + laneAhi) ^ swz) << 4);
            const uint32_t qb = (uint32_t)(((2 * ks + laneBhi) ^ swz) << 4);
            #pragma unroll
            for (int am = 0; am < 2; ++am) ldsm4(a_frag[am], aBase[am] + soC + qa);
            #pragma unroll
            for (int p = 0; p < 2; ++p)   ldsm4(b_frag[p],  bBase[p]  + soC + qb);
            #pragma unroll
            for (int am = 0; am < 2; ++am)
                #pragma unroll
                for (int an = 0; an < 4; ++an)
                    mma_f16(acc[am][an], a_frag[am], &b_frag[an >> 1][(an & 1) * 2]);
        }

        soC += STAGE_BYTES; if (soC == STAGES * STAGE_BYTES) soC = 0;
        soP += STAGE_BYTES; if (soP == STAGES * STAGE_BYTES) soP = 0;
    }

    // ---- epilogue: bias + store ----
    float2 bv[4];
    #pragma unroll
    for (int an = 0; an < 4; ++an)
        bv[an] = *reinterpret_cast<const float2*>(
            bias + colBase + warpN + an * 8 + (lane & 3) * 2);

    #pragma unroll
    for (int am = 0; am < 2; ++am) {
        const int r0 = rowBase + warpM + am * 16 + (lane >> 2);
        #pragma unroll
        for (int an = 0; an < 4; ++an) {
            const int col = colBase + warpN + an * 8 + (lane & 3) * 2;
            float2 lo = make_float2(acc[am][an][0] + bv[an].x, acc[am][an][1] + bv[an].y);
            float2 hi = make_float2(acc[am][an][2] + bv[an].x, acc[am][an][3] + bv[an].y);
            *reinterpret_cast<float2*>(C + (size_t)r0 * NDIM + col) = lo;
            *reinterpret_cast<float2*>(C + (size_t)(r0 + 8) * NDIM + col) = hi;
        }
    }
}

extern "C" void kernel_launch(void* const* d_in, const int* in_sizes, int n_in,
                              void* d_out, int out_size) {
    const float* x    = (const float*)d_in[0];   // [8,2048,4096]
    const float* w    = (const float*)d_in[1];   // [512,512,8]
    const float* bias = (const float*)d_in[2];   // [4096]
    float* out = (float*)d_out;                  // [16384,4096] fp32

    cudaFuncSetAttribute(gemm_mma_kernel,
                         cudaFuncAttributeMaxDynamicSharedMemorySize, GEMM_SMEM);

    conv_x_kernel<<<(int)(((size_t)MDIM * KDIM / 8) / 256), 256>>>(x);
    build_weff_kernel<<<(512 * 512 + 255) / 256, 256>>>(w);

    dim3 grid(NDIM / 64, MDIM / 128);            // (64, 128)
    gemm_mma_kernel<<<grid, 256, GEMM_SMEM>>>(bias, out);
}

// round 17
// speedup vs baseline: 1.1051x; 1.1051x over previous
#include <cuda_runtime.h>
#include <cuda_fp16.h>
#include <cstdint>

#define MDIM 16384
#define NDIM 4096
#define KDIM 4096

// Module-load scratch (allowed): fp16 copies of x and expanded weight.
__device__ __half g_xh[(size_t)MDIM * KDIM];    // 128 MB, [M, K] row-major
__device__ __half g_wh[(size_t)NDIM * KDIM];    // 32 MB,  [N, K] row-major

// ---------------------------------------------------------------------------
// helpers
// ---------------------------------------------------------------------------
__device__ __forceinline__ uint32_t smem_u32(const void* p) {
    uint32_t a;
    asm("{ .reg .u64 t; cvta.to.shared.u64 t, %1; cvt.u32.u64 %0, t; }" : "=r"(a) : "l"(p));
    return a;
}
__device__ __forceinline__ void cp16(uint32_t s, const void* g) {
    asm volatile("cp.async.cg.shared.global [%0], [%1], 16;" :: "r"(s), "l"(g) : "memory");
}
#define CP_COMMIT() asm volatile("cp.async.commit_group;" ::: "memory")

__device__ __forceinline__ void ldsm4(uint32_t* r, uint32_t addr) {
    asm volatile("ldmatrix.sync.aligned.m8n8.x4.shared.b16 {%0,%1,%2,%3}, [%4];"
        : "=r"(r[0]), "=r"(r[1]), "=r"(r[2]), "=r"(r[3]) : "r"(addr));
}
__device__ __forceinline__ void mma_f16(float* d, const uint32_t* a, const uint32_t* b) {
    asm volatile(
        "mma.sync.aligned.m16n8k16.row.col.f32.f16.f16.f32 "
        "{%0,%1,%2,%3}, {%4,%5,%6,%7}, {%8,%9}, {%0,%1,%2,%3};"
        : "+f"(d[0]), "+f"(d[1]), "+f"(d[2]), "+f"(d[3])
        : "r"(a[0]), "r"(a[1]), "r"(a[2]), "r"(a[3]), "r"(b[0]), "r"(b[1]));
}

// ---------------------------------------------------------------------------
// Kernel 0: convert x fp32 -> fp16 (RN). 8 elements per thread.
// ---------------------------------------------------------------------------
__global__ void conv_x_kernel(const float* __restrict__ x) {
    size_t i = (size_t)blockIdx.x * blockDim.x + threadIdx.x;
    float4 a = reinterpret_cast<const float4*>(x)[2 * i];
    float4 b = reinterpret_cast<const float4*>(x)[2 * i + 1];
    __half2 h0 = __floats2half2_rn(a.x, a.y);
    __half2 h1 = __floats2half2_rn(a.z, a.w);
    __half2 h2 = __floats2half2_rn(b.x, b.y);
    __half2 h3 = __floats2half2_rn(b.z, b.w);
    uint4 o;
    o.x = *reinterpret_cast<uint32_t*>(&h0);
    o.y = *reinterpret_cast<uint32_t*>(&h1);
    o.z = *reinterpret_cast<uint32_t*>(&h2);
    o.w = *reinterpret_cast<uint32_t*>(&h3);
    reinterpret_cast<uint4*>(g_xh)[i] = o;
}

// ---------------------------------------------------------------------------
// Kernel 1: expand octonion weight [512,512,8] -> w_eff [4096,4096] in fp16.
// ---------------------------------------------------------------------------
__global__ void build_weff_kernel(const float* __restrict__ w) {
    const signed char KTAB[64] = {
        0,1,2,3,4,5,6,7, 1,0,3,2,5,4,7,6, 2,3,0,1,6,7,4,5, 3,2,1,0,7,6,5,4,
        4,5,6,7,0,1,2,3, 5,4,7,6,1,0,3,2, 6,7,4,5,2,3,0,1, 7,6,5,4,3,2,1,0 };
    const signed char STAB[64] = {
        +1,+1,+1,+1,+1,+1,+1,+1, +1,-1,+1,-1,+1,-1,-1,+1, +1,-1,-1,+1,+1,+1,-1,-1,
        +1,+1,-1,-1,+1,-1,+1,-1, +1,-1,-1,-1,-1,+1,+1,+1, +1,+1,-1,+1,-1,-1,-1,+1,
        +1,+1,+1,-1,-1,+1,-1,-1, +1,-1,+1,+1,-1,-1,+1,-1 };

    int t = blockIdx.x * blockDim.x + threadIdx.x;
    if (t >= 512 * 512) return;
    int o = t >> 9, i = t & 511;

    const float4* wp = reinterpret_cast<const float4*>(w + (size_t)t * 8);
    float4 wlo = wp[0], whi = wp[1];
    float wv[8] = {wlo.x, wlo.y, wlo.z, wlo.w, whi.x, whi.y, whi.z, whi.w};

    #pragma unroll
    for (int k = 0; k < 8; ++k) {
        __half2 h[4];
        #pragma unroll
        for (int bp = 0; bp < 4; ++bp) {
            int b0 = 2 * bp, b1 = 2 * bp + 1;
            int a0 = KTAB[k * 8 + b0], a1 = KTAB[k * 8 + b1];
            float v0 = (float)STAB[a0 * 8 + b0] * wv[a0];
            float v1 = (float)STAB[a1 * 8 + b1] * wv[a1];
            h[bp] = __floats2half2_rn(v0, v1);
        }
        uint4 pk;
        pk.x = *reinterpret_cast<uint32_t*>(&h[0]);
        pk.y = *reinterpret_cast<uint32_t*>(&h[1]);
        pk.z = *reinterpret_cast<uint32_t*>(&h[2]);
        pk.w = *reinterpret_cast<uint32_t*>(&h[3]);
        *reinterpret_cast<uint4*>(g_wh + (size_t)(o * 8 + k) * KDIM + i * 8) = pk;
    }
}

// ---------------------------------------------------------------------------
// Kernel 2: fp16 mma.sync GEMM. C[M,N] = g_xh[M,K] @ g_wh[N,K]^T + bias.
// CTA 128x128, BK=64. 8 warps = 2(M) x 4(N); warp tile 64x32.
// 3-stage cp.async pipeline, 2 CTAs/SM. Register fragment double-buffering:
// k-step ks+1 fragments are loaded before ks MMAs issue.
// ---------------------------------------------------------------------------
#define BK 64
#define STAGES 3
#define A_BYTES (128 * 128)                 // 16384
#define STAGE_BYTES (2 * A_BYTES)           // 32768: [A | B]
#define GEMM_SMEM (STAGES * STAGE_BYTES)    // 98304
#define NTILES (KDIM / BK)                  // 64

__global__ __launch_bounds__(256, 2) void gemm_mma_kernel(
    const float* __restrict__ bias, float* __restrict__ C)
{
    extern __shared__ char smem[];
    const uint32_t sb = smem_u32(smem);
    const int tid  = threadIdx.x;
    const int lane = tid & 31;
    const int wid  = tid >> 5;
    const int rowBase = blockIdx.y * 128;    // M
    const int colBase = blockIdx.x * 128;    // N
    const int warpM = (wid >> 2) * 64;
    const int warpN = (wid & 3) * 32;

    // ---- global->shared load mapping: thread covers 4 A-chunks + 4 B-chunks ----
    const int lr  = tid >> 1;                // row 0..127
    const int lcp = (tid & 1) * 4;           // chunk base: 0 or 4 (chunk = 16 B)
    const __half* gA = g_xh + (size_t)(rowBase + lr) * KDIM + lcp * 8;
    const __half* gB = g_wh + (size_t)(colBase + lr) * KDIM + lcp * 8;
    uint32_t sAo[4], sBo[4];
    #pragma unroll
    for (int j = 0; j < 4; ++j) {
        uint32_t sw = (uint32_t)(((lcp + j) ^ (lr & 7)) << 4);
        sAo[j] = sb + lr * 128 + sw;
        sBo[j] = sb + A_BYTES + lr * 128 + sw;
    }

    // ---- ldmatrix address bases ----
    const int swz = lane & 7;
    uint32_t aBase[4], bBase[2];
    {
        int rA = warpM + (lane & 15);
        #pragma unroll
        for (int am = 0; am < 4; ++am) aBase[am] = sb + (uint32_t)((rA + am * 16) * 128);
        // B pair p covers n-atoms 2p,2p+1 (R6-verified mapping)
        int rB = warpN + (lane & 7) + ((lane >> 4) & 1) * 8;
        #pragma unroll
        for (int p = 0; p < 2; ++p)
            bBase[p] = sb + A_BYTES + (uint32_t)((rB + p * 16) * 128);
    }
    const int laneAhi = lane >> 4;           // A: k-chunk +0/+1 select
    const int laneBhi = (lane >> 3) & 1;     // B: k-chunk +0/+1 select

    float acc[4][4][4];
    #pragma unroll
    for (int am = 0; am < 4; ++am)
        #pragma unroll
        for (int an = 0; an < 4; ++an)
            #pragma unroll
            for (int e = 0; e < 4; ++e) acc[am][an][e] = 0.0f;

    // ---- prologue: prefetch tiles 0,1 into stages 0,1 ----
    #pragma unroll
    for (int t = 0; t < STAGES - 1; ++t) {
        uint32_t so = (uint32_t)(t * STAGE_BYTES);
        const __half* a = gA + t * BK;
        const __half* b = gB + t * BK;
        #pragma unroll
        for (int j = 0; j < 4; ++j) cp16(sAo[j] + so, a + j * 8);
        #pragma unroll
        for (int j = 0; j < 4; ++j) cp16(sBo[j] + so, b + j * 8);
        CP_COMMIT();
    }

    // double-buffered fragments
    uint32_t a_frag[2][4][4], b_frag[2][2][4];

    // ---- mainloop (stage offsets cycle 0,S,2S) ----
    uint32_t soC = 0;
    uint32_t soP = (STAGES - 1) * STAGE_BYTES;
    #pragma unroll 1
    for (int t = 0; t < NTILES; ++t) {
        asm volatile("cp.async.wait_group 1;" ::: "memory");
        __syncthreads();

        if (t + STAGES - 1 < NTILES) {
            int tn = t + STAGES - 1;
            const __half* a = gA + tn * BK;
            const __half* b = gB + tn * BK;
            #pragma unroll
            for (int j = 0; j < 4; ++j) cp16(sAo[j] + soP, a + j * 8);
            #pragma unroll
            for (int j = 0; j < 4; ++j) cp16(sBo[j] + soP, b + j * 8);
        }
        CP_COMMIT();

        // preload k-step 0 fragments into buffer 0
        {
            const uint32_t qa = (uint32_t)((laneAhi ^ swz) << 4);
            const uint32_t qb = (uint32_t)((laneBhi ^ swz) << 4);
            #pragma unroll
            for (int am = 0; am < 4; ++am) ldsm4(a_frag[0][am], aBase[am] + soC + qa);
            #pragma unroll
            for (int p = 0; p < 2; ++p)   ldsm4(b_frag[0][p],  bBase[p]  + soC + qb);
        }

        // 4 k16 steps; load ks+1 before computing ks
        #pragma unroll
        for (int ks = 0; ks < 4; ++ks) {
            const int cur = ks & 1;
            if (ks < 3) {
                const int nxt = cur ^ 1;
                const uint32_t qa = (uint32_t)(((2 * (ks + 1) + laneAhi) ^ swz) << 4);
                const uint32_t qb = (uint32_t)(((2 * (ks + 1) + laneBhi) ^ swz) << 4);
                #pragma unroll
                for (int am = 0; am < 4; ++am) ldsm4(a_frag[nxt][am], aBase[am] + soC + qa);
                #pragma unroll
                for (int p = 0; p < 2; ++p)   ldsm4(b_frag[nxt][p],  bBase[p]  + soC + qb);
            }
            #pragma unroll
            for (int am = 0; am < 4; ++am)
                #pragma unroll
                for (int an = 0; an < 4; ++an)
                    mma_f16(acc[am][an], a_frag[cur][am],
                            &b_frag[cur][an >> 1][(an & 1) * 2]);
        }

        soC += STAGE_BYTES; if (soC == STAGES * STAGE_BYTES) soC = 0;
        soP += STAGE_BYTES; if (soP == STAGES * STAGE_BYTES) soP = 0;
    }

    // ---- epilogue: bias + store ----
    float2 bv[4];
    #pragma unroll
    for (int an = 0; an < 4; ++an)
        bv[an] = *reinterpret_cast<const float2*>(
            bias + colBase + warpN + an * 8 + (lane & 3) * 2);

    #pragma unroll
    for (int am = 0; am < 4; ++am) {
        const int r0 = rowBase + warpM + am * 16 + (lane >> 2);
        #pragma unroll
        for (int an = 0; an < 4; ++an) {
            const int col = colBase + warpN + an * 8 + (lane & 3) * 2;
            float2 lo = make_float2(acc[am][an][0] + bv[an].x, acc[am][an][1] + bv[an].y);
            float2 hi = make_float2(acc[am][an][2] + bv[an].x, acc[am][an][3] + bv[an].y);
            *reinterpret_cast<float2*>(C + (size_t)r0 * NDIM + col) = lo;
            *reinterpret_cast<float2*>(C + (size_t)(r0 + 8) * NDIM + col) = hi;
        }
    }
}

extern "C" void kernel_launch(void* const* d_in, const int* in_sizes, int n_in,
                              void* d_out, int out_size) {
    const float* x    = (const float*)d_in[0];   // [8,2048,4096]
    const float* w    = (const float*)d_in[1];   // [512,512,8]
    const float* bias = (const float*)d_in[2];   // [4096]
    float* out = (float*)d_out;                  // [16384,4096] fp32

    cudaFuncSetAttribute(gemm_mma_kernel,
                         cudaFuncAttributeMaxDynamicSharedMemorySize, GEMM_SMEM);

    conv_x_kernel<<<(int)(((size_t)MDIM * KDIM / 8) / 256), 256>>>(x);
    build_weff_kernel<<<(512 * 512 + 255) / 256, 256>>>(w);

    dim3 grid(NDIM / 128, MDIM / 128);           // (32, 128)
    gemm_mma_kernel<<<grid, 256, GEMM_SMEM>>>(bias, out);
}